// round 15
// baseline (speedup 1.0000x reference)
#include <cuda_runtime.h>
#include <cuda_fp16.h>
#include <math.h>
#include <stdint.h>

#define BB 64
#define TT 512
#define VV 32000
#define DD 512
#define HH 1024
#define G4 4096  // 4*H
#define NBLK 128

// Scratch (allocation-free rule: __device__ globals only)
__device__ __half   g_xwh[(size_t)BB * TT * G4]; // 256 MB: xw = E[ids]@W + b (fp16)
__device__ __half   g_hh[2][BB * HH];            // ping-pong hidden state (fp16)
__device__ uint2    g_Uh[128 * 4 * 64 * 32];     // 8 MB: U fp16 fragment layout
__device__ uint2    g_Wh[512 * 32 * 32];         // 4 MB: W fp16 fragment layout
__device__ uint2    g_Eh[(size_t)VV * DD / 4];   // 32 MB: E in fp16
__device__ unsigned g_cnt0;                      // phase-0 (rows 0-31) barrier
__device__ unsigned g_cnt1;                      // phase-1 (rows 32-63) barrier

// SMEM layout (lstm_persist):
//   [0, 65536)         Us: U fragments [4 gates][64 k16][32 lanes] uint2
//   [65536, 196608)    A bufs: 2 phases x 4 chunks x 16 KB
//   [196608, 205824)   zs: float[4 gates][2 kseg][32 rows][9]
//   [205824, 205888)   8 mbarriers
#define US_OFF 0
#define A_OFF  65536
#define ZS_OFF 196608
#define MB_OFF 205824
#define SMEM_TOTAL 205952

__device__ __forceinline__ float sigf(float x) {
    return 1.0f / (1.0f + __expf(-x));
}

__device__ __forceinline__ void mma_f16(float d[4],
                                        uint32_t a0, uint32_t a1, uint32_t a2, uint32_t a3,
                                        uint32_t b0, uint32_t b1) {
    asm volatile(
        "mma.sync.aligned.m16n8k16.row.col.f32.f16.f16.f32 "
        "{%0,%1,%2,%3}, {%4,%5,%6,%7}, {%8,%9}, {%0,%1,%2,%3};\n"
        : "+f"(d[0]), "+f"(d[1]), "+f"(d[2]), "+f"(d[3])
        : "r"(a0), "r"(a1), "r"(a2), "r"(a3), "r"(b0), "r"(b1));
}

__device__ __forceinline__ void ldsm4(uint32_t& r0, uint32_t& r1, uint32_t& r2, uint32_t& r3,
                                      uint32_t saddr) {
    asm volatile("ldmatrix.sync.aligned.m8n8.x4.shared.b16 {%0,%1,%2,%3}, [%4];"
                 : "=r"(r0), "=r"(r1), "=r"(r2), "=r"(r3) : "r"(saddr));
}

__device__ __forceinline__ unsigned ld_acq(unsigned* p) {
    unsigned v;
    asm volatile("ld.acquire.gpu.u32 %0, [%1];" : "=r"(v) : "l"(p) : "memory");
    return v;
}

__device__ __forceinline__ uint32_t smem_u32(const void* p) {
    uint32_t a;
    asm("{ .reg .u64 t; cvta.to.shared.u64 t, %1; cvt.u32.u64 %0, t; }" : "=r"(a) : "l"(p));
    return a;
}

__device__ __forceinline__ void cp_async16(uint32_t dst_smem, const void* src) {
    asm volatile("cp.async.cg.shared.global [%0], [%1], 16;"
                 :: "r"(dst_smem), "l"(src) : "memory");
}

__device__ __forceinline__ void cp_async_arrive(uint32_t mbar) {
    asm volatile("cp.async.mbarrier.arrive.noinc.shared.b64 [%0];"
                 :: "r"(mbar) : "memory");
}

__device__ __forceinline__ void mbar_wait(uint32_t mbar, uint32_t parity) {
    asm volatile(
        "{\n\t.reg .pred P1;\n\t"
        "W_%=:\n\t"
        "mbarrier.try_wait.parity.acquire.cta.shared::cta.b64 P1, [%0], %1;\n\t"
        "@!P1 bra W_%=;\n\t}"
        :: "r"(mbar), "r"(parity) : "memory");
}

// lane-0 spin on a global counter, then warp-wide release
__device__ __forceinline__ void poll_ge(unsigned* p, unsigned tgt, int lane) {
    if (lane == 0) {
        while (ld_acq(p) < tgt) { }
    }
    __syncwarp();
}

// ---------------------------------------------------------------------------
__global__ void reset_bar() { g_cnt0 = 0; g_cnt1 = 0; }

__global__ void init_state() {
    int i = blockIdx.x * blockDim.x + threadIdx.x;
    if (i < BB * HH) g_hh[0][i] = __float2half(0.0f);
}

// ---------------------------------------------------------------------------
// pack_Eh: E fp32 -> fp16 (flat)
// ---------------------------------------------------------------------------
__global__ __launch_bounds__(256) void pack_Eh(const float* __restrict__ E) {
    size_t idx = (size_t)blockIdx.x * blockDim.x + threadIdx.x;
    float4 v = *(const float4*)&E[idx * 4];
    __half2 a = __floats2half2_rn(v.x, v.y);
    __half2 b = __floats2half2_rn(v.z, v.w);
    uint2 o;
    o.x = *(uint32_t*)&a;
    o.y = *(uint32_t*)&b;
    g_Eh[idx] = o;
}

// ---------------------------------------------------------------------------
// pack_Uh: U[1024][4096] -> [jb(128)][gate(4)][k16(64)][lane(32)] uint2 (fp16)
// ---------------------------------------------------------------------------
__global__ __launch_bounds__(256) void pack_Uh(const float* __restrict__ U) {
    int idx = blockIdx.x * blockDim.x + threadIdx.x;  // < 1048576
    int lane = idx & 31;
    int k16  = (idx >> 5) & 63;
    int gate = (idx >> 11) & 3;
    int jb   = idx >> 13;
    int col = gate * HH + jb * 8 + (lane >> 2);
    int r0  = k16 * 16 + (lane & 3) * 2;
    float u00 = U[(size_t)r0 * G4 + col];
    float u01 = U[(size_t)(r0 + 1) * G4 + col];
    float u10 = U[(size_t)(r0 + 8) * G4 + col];
    float u11 = U[(size_t)(r0 + 9) * G4 + col];
    __half2 h0 = __floats2half2_rn(u00, u01);
    __half2 h1 = __floats2half2_rn(u10, u11);
    uint2 v;
    v.x = *(uint32_t*)&h0;
    v.y = *(uint32_t*)&h1;
    g_Uh[idx] = v;
}

// ---------------------------------------------------------------------------
// pack_Wh: W[512][4096] -> [ntile(512)][k16(32)][lane(32)] uint2 (fp16)
// ---------------------------------------------------------------------------
__global__ __launch_bounds__(256) void pack_Wh(const float* __restrict__ W) {
    int idx = blockIdx.x * blockDim.x + threadIdx.x;  // < 524288
    int lane  = idx & 31;
    int k16   = (idx >> 5) & 31;
    int ntile = idx >> 10;
    int col = ntile * 8 + (lane >> 2);
    int r0  = k16 * 16 + (lane & 3) * 2;
    float u00 = W[(size_t)r0 * G4 + col];
    float u01 = W[(size_t)(r0 + 1) * G4 + col];
    float u10 = W[(size_t)(r0 + 8) * G4 + col];
    float u11 = W[(size_t)(r0 + 9) * G4 + col];
    __half2 h0 = __floats2half2_rn(u00, u01);
    __half2 h1 = __floats2half2_rn(u10, u11);
    uint2 v;
    v.x = *(uint32_t*)&h0;
    v.y = *(uint32_t*)&h1;
    g_Wh[idx] = v;
}

// ---------------------------------------------------------------------------
// embed GEMM (fp16 mma.sync m16n8k16): xw = E[ids] @ W + bias -> fp16
// ---------------------------------------------------------------------------
__global__ __launch_bounds__(256, 1) void embed_gemm_f16(
    const int* __restrict__ ids,
    const float* __restrict__ bias)
{
    __shared__ int ids_s[128];
    __shared__ __align__(16) char As[2][16384];  // 128 rows x 128B, x2

    const int m0 = blockIdx.y * 128;
    const int n0 = blockIdx.x * 128;
    const int tid  = threadIdx.x;
    const int warp = tid >> 5;
    const int lane = tid & 31;
    const int mw   = warp >> 2;
    const int nw   = warp & 3;

    if (tid < 128) ids_s[tid] = ids[m0 + tid];
    __syncthreads();

    const int base8 = (lane & 7) + ((lane >> 3) & 1) * 8;
    const int row7  = lane & 7;
    const int kh    = (lane >> 4) & 1;

    float d[4][4][4];
#pragma unroll
    for (int a = 0; a < 4; a++)
#pragma unroll
        for (int b = 0; b < 4; b++)
#pragma unroll
            for (int c = 0; c < 4; c++) d[a][b][c] = 0.0f;

    const uint4* Eh4 = (const uint4*)g_Eh;

    uint4 va[4];
#pragma unroll
    for (int i = 0; i < 4; i++) {
        int idx = tid + i * 256;
        int row = idx >> 3, u = idx & 7;
        va[i] = Eh4[(size_t)ids_s[row] * 64 + u];
    }
#pragma unroll
    for (int i = 0; i < 4; i++) {
        int idx = tid + i * 256;
        int row = idx >> 3, u = idx & 7;
        *(uint4*)(&As[0][row * 128 + ((u ^ (row & 7)) << 4)]) = va[i];
    }
    __syncthreads();

    const uint2* wp = &g_Wh[((size_t)(n0 >> 3) + nw * 4) * 32 * 32 + lane];

#pragma unroll 1
    for (int chunk = 0; chunk < 8; chunk++) {
        const int cur = chunk & 1;
        if (chunk < 7) {
            const int kq = (chunk + 1) * 8;
#pragma unroll
            for (int i = 0; i < 4; i++) {
                int idx = tid + i * 256;
                int row = idx >> 3, u = idx & 7;
                va[i] = Eh4[(size_t)ids_s[row] * 64 + kq + u];
            }
        }
        uint2 bfr[4][4];
#pragma unroll
        for (int nt = 0; nt < 4; nt++)
#pragma unroll
            for (int ki = 0; ki < 4; ki++)
                bfr[nt][ki] = wp[(size_t)nt * 1024 + (chunk * 4 + ki) * 32];

        uint32_t abase = (uint32_t)__cvta_generic_to_shared(&As[cur][0]);
#pragma unroll
        for (int ki = 0; ki < 4; ki++) {
#pragma unroll
            for (int mt = 0; mt < 4; mt++) {
                int rowb = mw * 64 + mt * 16 + base8;
                uint32_t a0, a1, a2, a3;
                ldsm4(a0, a1, a2, a3,
                      abase + rowb * 128 + (((2 * ki + kh) ^ row7) << 4));
#pragma unroll
                for (int nt = 0; nt < 4; nt++)
                    mma_f16(d[mt][nt], a0, a1, a2, a3,
                            bfr[nt][ki].x, bfr[nt][ki].y);
            }
        }
        if (chunk < 7) {
#pragma unroll
            for (int i = 0; i < 4; i++) {
                int idx = tid + i * 256;
                int row = idx >> 3, u = idx & 7;
                *(uint4*)(&As[cur ^ 1][row * 128 + ((u ^ (row & 7)) << 4)]) = va[i];
            }
        }
        __syncthreads();
    }

    // epilogue: + bias, write fp16 xw
    const int rr = lane >> 2;
    const int cc = (lane & 3) * 2;
#pragma unroll
    for (int nt = 0; nt < 4; nt++) {
        int col = n0 + nw * 32 + nt * 8 + cc;
        float2 bv = *(const float2*)&bias[col];
#pragma unroll
        for (int mt = 0; mt < 4; mt++) {
            int row = m0 + mw * 64 + mt * 16 + rr;
            __half2 v0 = __floats2half2_rn(d[mt][nt][0] + bv.x, d[mt][nt][1] + bv.y);
            __half2 v1 = __floats2half2_rn(d[mt][nt][2] + bv.x, d[mt][nt][3] + bv.y);
            *(__half2*)&g_xwh[(size_t)row * G4 + col] = v0;
            *(__half2*)&g_xwh[(size_t)(row + 8) * G4 + col] = v1;
        }
    }
}

// ---------------------------------------------------------------------------
// Persistent recurrence, two-phase batch-split pipeline.
// 128 blocks x 512 thr. Phase 0 = batch rows 0-31, phase 1 = rows 32-63,
// each with its OWN grid barrier; the wait for phase p's barrier is hidden
// behind the other phase's compute.
// Warp w: gate gt = w&3, m-tile mt = (w>>2)&1 (16 rows), K-seg ks = w>>3
// (512 k-cols). K-split partials summed in fusion.
// ---------------------------------------------------------------------------
__global__ __launch_bounds__(512, 1) void lstm_persist(
    const int* __restrict__ ids,
    float* __restrict__ out)
{
    extern __shared__ char smem_raw[];
    const uint32_t sbase = smem_u32(smem_raw);
    uint2* Us  = (uint2*)(smem_raw + US_OFF);   // [4][64][32]
    float* zsp = (float*)(smem_raw + ZS_OFF);   // [4][2][32][9]

    const int tid  = threadIdx.x;
    const int warp = tid >> 5;
    const int lane = tid & 31;
    const int jb   = blockIdx.x;
    const int j0   = jb * 8;

    // warp work assignment
    const int gt = warp & 3;
    const int mt = (warp >> 2) & 1;
    const int ks = warp >> 3;
    const int rowbase = mt * 16 + (lane & 7) + ((lane >> 3) & 1) * 8;
    const int row7    = rowbase & 7;
    const int khL     = (lane >> 4) & 1;
    const uint2* Ug = Us + gt * 2048 + lane;    // [64 k16][32 lanes]

    // Fusion mapping: thread -> (phase, b, j)
    const int ph_f = tid >> 8;                  // 0 or 1
    const int b_   = ph_f * 32 + ((tid & 255) >> 3);
    const int jj   = tid & 7;
    float c_reg = 0.0f, h_reg = 0.0f;

    // mbarriers: [phase*4 + chunk]
    const uint32_t mb0 = sbase + MB_OFF;
    if (tid == 0) {
#pragma unroll
        for (int c = 0; c < 8; c++)
            asm volatile("mbarrier.init.shared.b64 [%0], 512;"
                         :: "r"(mb0 + c * 8) : "memory");
    }

    // Load U slice once (64 KB)
    {
        const uint4* src = (const uint4*)&g_Uh[(size_t)jb * 4 * 64 * 32];
        uint4* dst = (uint4*)(smem_raw + US_OFF);
        for (int i = tid; i < 4096; i += 512) dst[i] = src[i];
    }
    __syncthreads();

    // prefetch xw + mask for t=0
    __half xh[4];
#pragma unroll
    for (int g = 0; g < 4; g++)
        xh[g] = __ldcg(&g_xwh[((size_t)(b_ * TT)) * G4 + g * HH + j0 + jj]);
    bool msk = __ldg(&ids[b_ * TT]) != 0;

#pragma unroll 1
    for (int t = 0; t < TT; t++) {
        const uint4* __restrict__ hin = (const uint4*)&g_hh[t & 1][0];
        __half* __restrict__ hout = &g_hh[(t + 1) & 1][0];
        const uint32_t parity = (uint32_t)(t & 1);
        const unsigned tgt = (unsigned)NBLK * (unsigned)t;

        // wait phase-0 h published (normally already satisfied), issue loads
        poll_ge(&g_cnt0, tgt, lane);
#pragma unroll
        for (int cc = 0; cc < 4; cc++) {
#pragma unroll
            for (int w = 0; w < 2; w++) {
                int idx = tid + w * 512;          // 0..1023
                int row = idx >> 5, u = idx & 31;
                uint32_t dst = sbase + A_OFF + cc * 16384 + row * 512
                             + ((u ^ (row & 7)) << 4);
                cp_async16(dst, &hin[row * 128 + cc * 32 + u]);
            }
            cp_async_arrive(mb0 + cc * 8);
        }
        // wait phase-1 h published, issue loads
        poll_ge(&g_cnt1, tgt, lane);
#pragma unroll
        for (int cc = 0; cc < 4; cc++) {
#pragma unroll
            for (int w = 0; w < 2; w++) {
                int idx = tid + w * 512;
                int row = idx >> 5, u = idx & 31;
                uint32_t dst = sbase + A_OFF + 65536 + cc * 16384 + row * 512
                             + ((u ^ (row & 7)) << 4);
                cp_async16(dst, &hin[(32 + row) * 128 + cc * 32 + u]);
            }
            cp_async_arrive(mb0 + (4 + cc) * 8);
        }

        // prefetch next step's xw + mask (independent of h)
        __half xhn[4];
        bool mskn = false;
        if (t < TT - 1) {
#pragma unroll
            for (int g = 0; g < 4; g++)
                xhn[g] = __ldcg(&g_xwh[((size_t)(b_ * TT + t + 1)) * G4 + g * HH + j0 + jj]);
            mskn = __ldg(&ids[b_ * TT + t + 1]) != 0;
        }

        // ================= two phases =================
#pragma unroll
        for (int ph = 0; ph < 2; ph++) {
            float d[4];
#pragma unroll
            for (int j = 0; j < 4; j++) d[j] = 0.0f;

#pragma unroll
            for (int cq = 0; cq < 2; cq++) {
                int cc = 2 * ks + cq;
                mbar_wait(mb0 + (ph * 4 + cc) * 8, parity);
                uint32_t abase = sbase + A_OFF + ph * 65536 + cc * 16384
                               + rowbase * 512;
#pragma unroll
                for (int ki = 0; ki < 16; ki++) {
                    uint32_t a0, a1, a2, a3;
                    ldsm4(a0, a1, a2, a3, abase + (((2 * ki + khL) ^ row7) << 4));
                    uint2 b = Ug[(cc * 16 + ki) * 32];
                    mma_f16(d, a0, a1, a2, a3, b.x, b.y);
                }
            }

            // z exchange: zs[gt][ks][row][col]
            {
                int r = lane >> 2;
                int c2 = (lane & 3) * 2;
                float* zr = zsp + gt * 576 + ks * 288;
                zr[(mt * 16 + r) * 9 + c2]         = d[0];
                zr[(mt * 16 + r) * 9 + c2 + 1]     = d[1];
                zr[(mt * 16 + 8 + r) * 9 + c2]     = d[2];
                zr[(mt * 16 + 8 + r) * 9 + c2 + 1] = d[3];
            }
            __syncthreads();

            // fusion: threads of this phase only (256 threads, 1 item each)
            if (ph_f == ph) {
                int b31 = b_ & 31;
                float zi = zsp[0 * 576 + b31 * 9 + jj] + zsp[0 * 576 + 288 + b31 * 9 + jj]
                         + __half2float(xh[0]);
                float zf = zsp[1 * 576 + b31 * 9 + jj] + zsp[1 * 576 + 288 + b31 * 9 + jj]
                         + __half2float(xh[1]);
                float zg = zsp[2 * 576 + b31 * 9 + jj] + zsp[2 * 576 + 288 + b31 * 9 + jj]
                         + __half2float(xh[2]);
                float zo = zsp[3 * 576 + b31 * 9 + jj] + zsp[3 * 576 + 288 + b31 * 9 + jj]
                         + __half2float(xh[3]);

                float ig = sigf(zi);
                float fg = sigf(zf);
                float gg = sigf(zg);   // reference: sigmoid (not tanh)
                float og = sigf(zo);

                float cn = fmaf(fg, c_reg, ig * gg);
                float hn = og * sigf(cn);

                float hv = msk ? hn : h_reg;
                float cv = msk ? cn : c_reg;
                h_reg = hv;
                c_reg = cv;

                hout[b_ * HH + j0 + jj] = __float2half(hv);
                __stcg(&out[((size_t)(b_ * TT + t)) * HH + j0 + jj], hv);
                if (t == TT - 1) {
                    __stcg(&out[(size_t)BB * TT * HH + b_ * HH + j0 + jj], hv);
                    __stcg(&out[(size_t)BB * TT * HH + BB * HH + b_ * HH + j0 + jj], cv);
                }
            }
            __syncthreads();

            // publish this phase's h (fire-and-forget; nobody waits here)
            if (tid == 0) {
                asm volatile("red.release.gpu.global.add.u32 [%0], 1;"
                             :: "l"(ph == 0 ? &g_cnt0 : &g_cnt1) : "memory");
            }
        }

        // rotate prefetched xw/mask
#pragma unroll
        for (int g = 0; g < 4; g++) xh[g] = xhn[g];
        msk = mskn;
    }
}

extern "C" void kernel_launch(void* const* d_in, const int* in_sizes, int n_in,
                              void* d_out, int out_size) {
    const int*   ids  = (const int*)d_in[0];
    const float* E    = (const float*)d_in[1];
    const float* W    = (const float*)d_in[2];
    const float* U    = (const float*)d_in[3];
    const float* bias = (const float*)d_in[4];
    float* out = (float*)d_out;

    static bool attr_set = false;
    if (!attr_set) {
        cudaFuncSetAttribute(lstm_persist,
                             cudaFuncAttributeMaxDynamicSharedMemorySize, SMEM_TOTAL);
        attr_set = true;
    }

    reset_bar<<<1, 1>>>();
    init_state<<<(BB * HH + 255) / 256, 256>>>();
    pack_Eh<<<VV * DD / 4 / 256, 256>>>(E);
    pack_Uh<<<4096, 256>>>(U);
    pack_Wh<<<2048, 256>>>(W);

    dim3 g1(G4 / 128, (BB * TT) / 128);  // (32, 256)
    embed_gemm_f16<<<g1, 256>>>(ids, bias);

    lstm_persist<<<NBLK, 512, SMEM_TOTAL>>>(ids, out);
}

// round 16
// speedup vs baseline: 2.1550x; 2.1550x over previous
#include <cuda_runtime.h>
#include <cuda_fp16.h>
#include <math.h>
#include <stdint.h>

#define BB 64
#define TT 512
#define VV 32000
#define DD 512
#define HH 1024
#define G4 4096  // 4*H
#define NBLK 128

// Scratch (allocation-free rule: __device__ globals only)
__device__ __half   g_xwh[(size_t)BB * TT * G4]; // 256 MB: xw = E[ids]@W + b (fp16)
__device__ __half   g_hh[2][BB * HH];            // ping-pong hidden state (fp16)
__device__ uint2    g_Uh[128 * 4 * 64 * 32];     // 8 MB: U fp16 fragment layout
__device__ uint2    g_Wh[512 * 32 * 32];         // 4 MB: W fp16 fragment layout
__device__ uint2    g_Eh[(size_t)VV * DD / 4];   // 32 MB: E in fp16
__device__ unsigned g_cnt;

// SMEM layout (lstm_persist):
//   [0, 131072)        A bufs: 4 chunks x 32 KB
//   [131072, 196608)   zs: float[8 kseg][4 gates][64 rows][8]
//   [196608, 196640)   4 mbarriers
#define A_OFF  0
#define ZS_OFF 131072
#define MB_OFF 196608
#define SMEM_TOTAL 196736

__device__ __forceinline__ float sigf(float x) {
    return 1.0f / (1.0f + __expf(-x));
}

__device__ __forceinline__ void mma_f16(float d[4],
                                        uint32_t a0, uint32_t a1, uint32_t a2, uint32_t a3,
                                        uint32_t b0, uint32_t b1) {
    asm volatile(
        "mma.sync.aligned.m16n8k16.row.col.f32.f16.f16.f32 "
        "{%0,%1,%2,%3}, {%4,%5,%6,%7}, {%8,%9}, {%0,%1,%2,%3};\n"
        : "+f"(d[0]), "+f"(d[1]), "+f"(d[2]), "+f"(d[3])
        : "r"(a0), "r"(a1), "r"(a2), "r"(a3), "r"(b0), "r"(b1));
}

__device__ __forceinline__ void ldsm4(uint32_t& r0, uint32_t& r1, uint32_t& r2, uint32_t& r3,
                                      uint32_t saddr) {
    asm volatile("ldmatrix.sync.aligned.m8n8.x4.shared.b16 {%0,%1,%2,%3}, [%4];"
                 : "=r"(r0), "=r"(r1), "=r"(r2), "=r"(r3) : "r"(saddr));
}

__device__ __forceinline__ unsigned ld_acq(unsigned* p) {
    unsigned v;
    asm volatile("ld.acquire.gpu.u32 %0, [%1];" : "=r"(v) : "l"(p) : "memory");
    return v;
}

__device__ __forceinline__ uint32_t smem_u32(const void* p) {
    uint32_t a;
    asm("{ .reg .u64 t; cvta.to.shared.u64 t, %1; cvt.u32.u64 %0, t; }" : "=r"(a) : "l"(p));
    return a;
}

__device__ __forceinline__ void cp_async16(uint32_t dst_smem, const void* src) {
    asm volatile("cp.async.cg.shared.global [%0], [%1], 16;"
                 :: "r"(dst_smem), "l"(src) : "memory");
}

__device__ __forceinline__ void cp_async_arrive(uint32_t mbar) {
    asm volatile("cp.async.mbarrier.arrive.noinc.shared.b64 [%0];"
                 :: "r"(mbar) : "memory");
}

__device__ __forceinline__ void mbar_wait(uint32_t mbar, uint32_t parity) {
    asm volatile(
        "{\n\t.reg .pred P1;\n\t"
        "W_%=:\n\t"
        "mbarrier.try_wait.parity.acquire.cta.shared::cta.b64 P1, [%0], %1;\n\t"
        "@!P1 bra W_%=;\n\t}"
        :: "r"(mbar), "r"(parity) : "memory");
}

// ---------------------------------------------------------------------------
__global__ void reset_bar() { g_cnt = 0; }

__global__ void init_state() {
    int i = blockIdx.x * blockDim.x + threadIdx.x;
    if (i < BB * HH) g_hh[0][i] = __float2half(0.0f);
}

// ---------------------------------------------------------------------------
// pack_Eh: E fp32 -> fp16 (flat)
// ---------------------------------------------------------------------------
__global__ __launch_bounds__(256) void pack_Eh(const float* __restrict__ E) {
    size_t idx = (size_t)blockIdx.x * blockDim.x + threadIdx.x;
    float4 v = *(const float4*)&E[idx * 4];
    __half2 a = __floats2half2_rn(v.x, v.y);
    __half2 b = __floats2half2_rn(v.z, v.w);
    uint2 o;
    o.x = *(uint32_t*)&a;
    o.y = *(uint32_t*)&b;
    g_Eh[idx] = o;
}

// ---------------------------------------------------------------------------
// pack_Uh: U[1024][4096] -> [jb(128)][gate(4)][k16(64)][lane(32)] uint2 (fp16)
// ---------------------------------------------------------------------------
__global__ __launch_bounds__(256) void pack_Uh(const float* __restrict__ U) {
    int idx = blockIdx.x * blockDim.x + threadIdx.x;  // < 1048576
    int lane = idx & 31;
    int k16  = (idx >> 5) & 63;
    int gate = (idx >> 11) & 3;
    int jb   = idx >> 13;
    int col = gate * HH + jb * 8 + (lane >> 2);
    int r0  = k16 * 16 + (lane & 3) * 2;
    float u00 = U[(size_t)r0 * G4 + col];
    float u01 = U[(size_t)(r0 + 1) * G4 + col];
    float u10 = U[(size_t)(r0 + 8) * G4 + col];
    float u11 = U[(size_t)(r0 + 9) * G4 + col];
    __half2 h0 = __floats2half2_rn(u00, u01);
    __half2 h1 = __floats2half2_rn(u10, u11);
    uint2 v;
    v.x = *(uint32_t*)&h0;
    v.y = *(uint32_t*)&h1;
    g_Uh[idx] = v;
}

// ---------------------------------------------------------------------------
// pack_Wh: W[512][4096] -> [ntile(512)][k16(32)][lane(32)] uint2 (fp16)
// ---------------------------------------------------------------------------
__global__ __launch_bounds__(256) void pack_Wh(const float* __restrict__ W) {
    int idx = blockIdx.x * blockDim.x + threadIdx.x;  // < 524288
    int lane  = idx & 31;
    int k16   = (idx >> 5) & 31;
    int ntile = idx >> 10;
    int col = ntile * 8 + (lane >> 2);
    int r0  = k16 * 16 + (lane & 3) * 2;
    float u00 = W[(size_t)r0 * G4 + col];
    float u01 = W[(size_t)(r0 + 1) * G4 + col];
    float u10 = W[(size_t)(r0 + 8) * G4 + col];
    float u11 = W[(size_t)(r0 + 9) * G4 + col];
    __half2 h0 = __floats2half2_rn(u00, u01);
    __half2 h1 = __floats2half2_rn(u10, u11);
    uint2 v;
    v.x = *(uint32_t*)&h0;
    v.y = *(uint32_t*)&h1;
    g_Wh[idx] = v;
}

// ---------------------------------------------------------------------------
// embed GEMM (fp16 mma.sync m16n8k16): xw = E[ids] @ W + bias -> fp16
// ---------------------------------------------------------------------------
__global__ __launch_bounds__(256, 1) void embed_gemm_f16(
    const int* __restrict__ ids,
    const float* __restrict__ bias)
{
    __shared__ int ids_s[128];
    __shared__ __align__(16) char As[2][16384];  // 128 rows x 128B, x2

    const int m0 = blockIdx.y * 128;
    const int n0 = blockIdx.x * 128;
    const int tid  = threadIdx.x;
    const int warp = tid >> 5;
    const int lane = tid & 31;
    const int mw   = warp >> 2;
    const int nw   = warp & 3;

    if (tid < 128) ids_s[tid] = ids[m0 + tid];
    __syncthreads();

    const int base8 = (lane & 7) + ((lane >> 3) & 1) * 8;
    const int row7  = lane & 7;
    const int kh    = (lane >> 4) & 1;

    float d[4][4][4];
#pragma unroll
    for (int a = 0; a < 4; a++)
#pragma unroll
        for (int b = 0; b < 4; b++)
#pragma unroll
            for (int c = 0; c < 4; c++) d[a][b][c] = 0.0f;

    const uint4* Eh4 = (const uint4*)g_Eh;

    uint4 va[4];
#pragma unroll
    for (int i = 0; i < 4; i++) {
        int idx = tid + i * 256;
        int row = idx >> 3, u = idx & 7;
        va[i] = Eh4[(size_t)ids_s[row] * 64 + u];
    }
#pragma unroll
    for (int i = 0; i < 4; i++) {
        int idx = tid + i * 256;
        int row = idx >> 3, u = idx & 7;
        *(uint4*)(&As[0][row * 128 + ((u ^ (row & 7)) << 4)]) = va[i];
    }
    __syncthreads();

    const uint2* wp = &g_Wh[((size_t)(n0 >> 3) + nw * 4) * 32 * 32 + lane];

#pragma unroll 1
    for (int chunk = 0; chunk < 8; chunk++) {
        const int cur = chunk & 1;
        if (chunk < 7) {
            const int kq = (chunk + 1) * 8;
#pragma unroll
            for (int i = 0; i < 4; i++) {
                int idx = tid + i * 256;
                int row = idx >> 3, u = idx & 7;
                va[i] = Eh4[(size_t)ids_s[row] * 64 + kq + u];
            }
        }
        uint2 bfr[4][4];
#pragma unroll
        for (int nt = 0; nt < 4; nt++)
#pragma unroll
            for (int ki = 0; ki < 4; ki++)
                bfr[nt][ki] = wp[(size_t)nt * 1024 + (chunk * 4 + ki) * 32];

        uint32_t abase = (uint32_t)__cvta_generic_to_shared(&As[cur][0]);
#pragma unroll
        for (int ki = 0; ki < 4; ki++) {
#pragma unroll
            for (int mt = 0; mt < 4; mt++) {
                int rowb = mw * 64 + mt * 16 + base8;
                uint32_t a0, a1, a2, a3;
                ldsm4(a0, a1, a2, a3,
                      abase + rowb * 128 + (((2 * ki + kh) ^ row7) << 4));
#pragma unroll
                for (int nt = 0; nt < 4; nt++)
                    mma_f16(d[mt][nt], a0, a1, a2, a3,
                            bfr[nt][ki].x, bfr[nt][ki].y);
            }
        }
        if (chunk < 7) {
#pragma unroll
            for (int i = 0; i < 4; i++) {
                int idx = tid + i * 256;
                int row = idx >> 3, u = idx & 7;
                *(uint4*)(&As[cur ^ 1][row * 128 + ((u ^ (row & 7)) << 4)]) = va[i];
            }
        }
        __syncthreads();
    }

    // epilogue: + bias, write fp16 xw
    const int rr = lane >> 2;
    const int cc = (lane & 3) * 2;
#pragma unroll
    for (int nt = 0; nt < 4; nt++) {
        int col = n0 + nw * 32 + nt * 8 + cc;
        float2 bv = *(const float2*)&bias[col];
#pragma unroll
        for (int mt = 0; mt < 4; mt++) {
            int row = m0 + mw * 64 + mt * 16 + rr;
            __half2 v0 = __floats2half2_rn(d[mt][nt][0] + bv.x, d[mt][nt][1] + bv.y);
            __half2 v1 = __floats2half2_rn(d[mt][nt][2] + bv.x, d[mt][nt][3] + bv.y);
            *(__half2*)&g_xwh[(size_t)row * G4 + col] = v0;
            *(__half2*)&g_xwh[(size_t)(row + 8) * G4 + col] = v1;
        }
    }
}

// ---------------------------------------------------------------------------
// Persistent recurrence (fp16 MMA, register-resident U).
// 128 blocks x 512 thr. Warp w = (kseg ks = w>>1 in 0..7, mhalf mp = w&1).
// Each warp: 32 rows (mp) x 128 k (ks) x ALL 4 gates; U fragments for its
// k-range live in 64 registers for the whole kernel (zero B smem traffic).
// Each warp consumes exactly one cp.async chunk (ks>>1). z partials summed
// over ksegs in fusion.
// ---------------------------------------------------------------------------
__global__ __launch_bounds__(512, 1) void lstm_persist(
    const int* __restrict__ ids,
    float* __restrict__ out)
{
    extern __shared__ char smem_raw[];
    const uint32_t sbase = smem_u32(smem_raw);
    float* zsp = (float*)(smem_raw + ZS_OFF);   // [8 ks][4 g][64 rows][8]

    const int tid  = threadIdx.x;
    const int warp = tid >> 5;
    const int lane = tid & 31;
    const int jb   = blockIdx.x;
    const int j0   = jb * 8;

    // warp work assignment
    const int ks = warp >> 1;          // k-segment: k16 in [ks*8, ks*8+8)
    const int mp = warp & 1;           // row half: rows [mp*32, mp*32+32)
    const int cc = ks >> 1;            // cp.async chunk this warp consumes
    const int kib = (ks & 1) * 8;      // ki offset within chunk
    const int base8 = (lane & 7) + ((lane >> 3) & 1) * 8;
    const int row7  = lane & 7;
    const int khL   = (lane >> 4) & 1;

    // Register-resident U fragments: Bu[gate][kk] for this warp's k-range
    uint2 Bu[4][8];
#pragma unroll
    for (int g = 0; g < 4; g++)
#pragma unroll
        for (int kk = 0; kk < 8; kk++)
            Bu[g][kk] = g_Uh[(((size_t)jb * 4 + g) * 64 + ks * 8 + kk) * 32 + lane];

    // Fusion: one (b, j) item per thread
    const int b_ = tid >> 3;
    const int jj = tid & 7;
    float c_reg = 0.0f, h_reg = 0.0f;

    // mbarriers (one per chunk)
    const uint32_t mb0 = sbase + MB_OFF;
    if (tid == 0) {
#pragma unroll
        for (int c = 0; c < 4; c++)
            asm volatile("mbarrier.init.shared.b64 [%0], 512;"
                         :: "r"(mb0 + c * 8) : "memory");
    }
    __syncthreads();

    // prefetch xw + mask for t=0
    __half xh[4];
#pragma unroll
    for (int g = 0; g < 4; g++)
        xh[g] = __ldcg(&g_xwh[((size_t)(b_ * TT)) * G4 + g * HH + j0 + jj]);
    bool msk = __ldg(&ids[b_ * TT]) != 0;

#pragma unroll 1
    for (int t = 0; t < TT; t++) {
        const uint4* __restrict__ hin = (const uint4*)&g_hh[t & 1][0];
        __half* __restrict__ hout = &g_hh[(t + 1) & 1][0];
        const uint32_t parity = (uint32_t)(t & 1);

        // issue ALL chunks' cp.asyncs with per-chunk mbarrier arrives
#pragma unroll
        for (int c = 0; c < 4; c++) {
#pragma unroll
            for (int w = 0; w < 4; w++) {
                int idx = tid + w * 512;          // 0..2047
                int row = idx >> 5, u = idx & 31;
                uint32_t dst = sbase + A_OFF + c * 32768 + row * 512
                             + ((u ^ (row & 7)) << 4);
                cp_async16(dst, &hin[row * 128 + c * 32 + u]);
            }
            cp_async_arrive(mb0 + c * 8);
        }

        // prefetch next step's xw + mask (overlaps async streaming + MMA)
        __half xhn[4];
        bool mskn = false;
        if (t < TT - 1) {
#pragma unroll
            for (int g = 0; g < 4; g++)
                xhn[g] = __ldcg(&g_xwh[((size_t)(b_ * TT + t + 1)) * G4 + g * HH + j0 + jj]);
            mskn = __ldg(&ids[b_ * TT + t + 1]) != 0;
        }

        float d[2][4][4];  // [mtl][gate][reg]
#pragma unroll
        for (int i = 0; i < 2; i++)
#pragma unroll
            for (int g = 0; g < 4; g++)
#pragma unroll
                for (int j = 0; j < 4; j++) d[i][g][j] = 0.0f;

        // wait for this warp's chunk, then 16 ldsm + 64 MMA
        mbar_wait(mb0 + cc * 8, parity);
        {
            uint32_t ab = sbase + A_OFF + cc * 32768;
#pragma unroll
            for (int kk = 0; kk < 8; kk++) {
                int ki = kib + kk;
                uint32_t koff = (uint32_t)(((2 * ki + khL) ^ row7) << 4);
#pragma unroll
                for (int mtl = 0; mtl < 2; mtl++) {
                    int rowb = mp * 32 + mtl * 16 + base8;
                    uint32_t a0, a1, a2, a3;
                    ldsm4(a0, a1, a2, a3, ab + rowb * 512 + koff);
#pragma unroll
                    for (int g = 0; g < 4; g++)
                        mma_f16(d[mtl][g], a0, a1, a2, a3,
                                Bu[g][kk].x, Bu[g][kk].y);
                }
            }
        }

        // z exchange: zs[ks][g][row][col] partials
        {
            int r = lane >> 2;
            int c2 = (lane & 3) * 2;
#pragma unroll
            for (int mtl = 0; mtl < 2; mtl++) {
                int row0 = mp * 32 + mtl * 16;
#pragma unroll
                for (int g = 0; g < 4; g++) {
                    float* zr = zsp + ((ks * 4 + g) * 64) * 8;
                    *(float2*)&zr[(row0 + r) * 8 + c2] =
                        make_float2(d[mtl][g][0], d[mtl][g][1]);
                    *(float2*)&zr[(row0 + 8 + r) * 8 + c2] =
                        make_float2(d[mtl][g][2], d[mtl][g][3]);
                }
            }
        }
        __syncthreads();

        // gate fusion: all 512 threads, one (b, j) each; sum 8 kseg partials
        {
            float zsum[4];
#pragma unroll
            for (int g = 0; g < 4; g++) zsum[g] = __half2float(xh[g]);
#pragma unroll
            for (int s = 0; s < 8; s++)
#pragma unroll
                for (int g = 0; g < 4; g++)
                    zsum[g] += zsp[((s * 4 + g) * 64 + b_) * 8 + jj];

            float ig = sigf(zsum[0]);
            float fg = sigf(zsum[1]);
            float gg = sigf(zsum[2]);   // reference: sigmoid (not tanh)
            float og = sigf(zsum[3]);

            float cn = fmaf(fg, c_reg, ig * gg);
            float hn = og * sigf(cn);

            float hv = msk ? hn : h_reg;
            float cv = msk ? cn : c_reg;
            h_reg = hv;
            c_reg = cv;

            hout[b_ * HH + j0 + jj] = __float2half(hv);
            __stcg(&out[((size_t)(b_ * TT + t)) * HH + j0 + jj], hv);
            if (t == TT - 1) {
                __stcg(&out[(size_t)BB * TT * HH + b_ * HH + j0 + jj], hv);
                __stcg(&out[(size_t)BB * TT * HH + BB * HH + b_ * HH + j0 + jj], cv);
            }
        }

        // rotate prefetched xw/mask
#pragma unroll
        for (int g = 0; g < 4; g++) xh[g] = xhn[g];
        msk = mskn;

        // grid barrier: single counter (also orders zs reads before next
        // step's z writes, and h stores before next cp.asyncs)
        __syncthreads();
        if (tid == 0) {
            asm volatile("red.release.gpu.global.add.u32 [%0], 1;"
                         :: "l"(&g_cnt) : "memory");
            unsigned tgt = (unsigned)NBLK * (unsigned)(t + 1);
            while (ld_acq(&g_cnt) < tgt) { }
        }
        __syncthreads();
    }
}

extern "C" void kernel_launch(void* const* d_in, const int* in_sizes, int n_in,
                              void* d_out, int out_size) {
    const int*   ids  = (const int*)d_in[0];
    const float* E    = (const float*)d_in[1];
    const float* W    = (const float*)d_in[2];
    const float* U    = (const float*)d_in[3];
    const float* bias = (const float*)d_in[4];
    float* out = (float*)d_out;

    static bool attr_set = false;
    if (!attr_set) {
        cudaFuncSetAttribute(lstm_persist,
                             cudaFuncAttributeMaxDynamicSharedMemorySize, SMEM_TOTAL);
        attr_set = true;
    }

    reset_bar<<<1, 1>>>();
    init_state<<<(BB * HH + 255) / 256, 256>>>();
    pack_Eh<<<VV * DD / 4 / 256, 256>>>(E);
    pack_Uh<<<4096, 256>>>(U);
    pack_Wh<<<2048, 256>>>(W);

    dim3 g1(G4 / 128, (BB * TT) / 128);  // (32, 256)
    embed_gemm_f16<<<g1, 256>>>(ids, bias);

    lstm_persist<<<NBLK, 512, SMEM_TOTAL>>>(ids, out);
}